// round 16
// baseline (speedup 1.0000x reference)
#include <cuda_runtime.h>
#include <cuda_bf16.h>
#include <cuda_fp16.h>
#include <math.h>
#include <stdint.h>

#define Bsz   64
#define FND   512
#define LLEN  768
#define CC    (FND*LLEN)        /* 393216 */
#define BCN   (Bsz*CC)          /* 25165824 */
#define DFT_N 768               /* 384 bins x (cos,sin) interleaved */
#define NBINS 385
#define NMAX  192               /* max patches (p>=4) */
#define DFT_M 32768             /* B*FN rows */
#define PRJ_M 49152             /* B*L rows */

// ---------------- static device scratch ------------------------------------
__device__ float g_big[DFT_M*384];        // DFT |F| (32768x384) fp32
__device__ float g_xn[BCN];               // proj2 out P (49152x512)
__device__ float g_xt[BCN];               // xt (B,L,FN)
__device__ float g_fused[BCN];            // out_pre (B,FN,L) for BN2
__device__ __half g_h2a[Bsz*NMAX*16*FND]; // patch-MLP out, branch 0 (fp16)
__device__ __half g_h2b[Bsz*NMAX*16*FND]; // branch 1
__device__ __half g_h2c[Bsz*NMAX*16*FND]; // branch 2
__device__ float g_mean[CC];
__device__ float g_rstd[CC];
__device__ float g_part[128*384];
__device__ float g_freq[NBINS];
__device__ float g_M1[3][384*32];
__device__ int   g_pp[3], g_pn[3], g_poff[3];
__device__ float g_pw[3];
__device__ uint32_t g_mask[3][96];        // used-row bitmask per branch

// fp16 GEMM operands (single pass everywhere)
__device__ __half g_xnh[BCN];             // DFT A (32768x768)
__device__ __half g_trigh[DFT_N*LLEN];    // DFT B [768][768]
__device__ __half g_fh[BCN];              // proj1 A (49152x512)
__device__ __half g_g1h[PRJ_M*1024];      // proj1 out / proj2 A
__device__ __half g_wp1h[1024*512];       // Wp1^T
__device__ __half g_wp2h[512*1024];       // Wp2^T

__device__ __forceinline__ float gelu_f(float x){
    return 0.5f*x*(1.0f + erff(x*0.70710678118654752440f));
}
__device__ __forceinline__ uint32_t smem_u32(const void* p){
    uint32_t a;
    asm("{ .reg .u64 t; cvta.to.shared.u64 t, %1; cvt.u32.u64 %0, t; }" : "=r"(a) : "l"(p));
    return a;
}
// shared resize-position helper (mask & fuse3 bit-identical by construction)
__device__ __forceinline__ float pos_of(int l, int T2){
    float s = (float)T2 * (1.0f/768.0f);
    float pos = fmaf((float)l + 0.5f, s, -0.5f);
    return fminf(fmaxf(pos, 0.0f), (float)(T2-1));
}

// ================= warp-MMA GEMM (m16n8k16 fp16 + ldmatrix) ================
// Block 128x128, 4 warps (2x2), warp tile 64x64, 3-stage cp.async pipeline,
// XOR-swizzled 64B smem rows. Single fp16 pass for all modes.
// MODE 0: DFT   A=g_xnh  B=g_trigh K=768  N=768   out |F| fp32 g_big
// MODE 1: proj1 A=g_fh   B=g_wp1h  K=512  N=1024  out fp16 g_g1h (bias+gelu)
// MODE 2: proj2 A=g_g1h  B=g_wp2h  K=1024 N=512   out fp32 g_xn (bias)
#define KC     32
#define STGB   8192

__device__ __forceinline__ void mma_f16(float* c, const uint32_t* a, const uint32_t* b){
    asm volatile(
        "mma.sync.aligned.m16n8k16.row.col.f32.f16.f16.f32 "
        "{%0,%1,%2,%3}, {%4,%5,%6,%7}, {%8,%9}, {%0,%1,%2,%3};"
        : "+f"(c[0]), "+f"(c[1]), "+f"(c[2]), "+f"(c[3])
        : "r"(a[0]), "r"(a[1]), "r"(a[2]), "r"(a[3]), "r"(b[0]), "r"(b[1]));
}
__device__ __forceinline__ void ldsm4(uint32_t* r, uint32_t addr){
    asm volatile("ldmatrix.sync.aligned.m8n8.x4.shared.b16 {%0,%1,%2,%3}, [%4];"
        : "=r"(r[0]), "=r"(r[1]), "=r"(r[2]), "=r"(r[3]) : "r"(addr));
}

template<int MODE>
__global__ void __launch_bounds__(128, 3)
gemm_wm(const float* __restrict__ bias)
{
    constexpr int K  = (MODE==0) ? 768 : (MODE==1) ? 512 : 1024;
    constexpr int N  = (MODE==0) ? 768 : (MODE==1) ? 1024 : 512;
    constexpr int NC = K / KC;

    const uint16_t* A = (MODE==0) ? (const uint16_t*)g_xnh :
                        (MODE==1) ? (const uint16_t*)g_fh  : (const uint16_t*)g_g1h;
    const uint16_t* B = (MODE==0) ? (const uint16_t*)g_trigh :
                        (MODE==1) ? (const uint16_t*)g_wp1h : (const uint16_t*)g_wp2h;

    __shared__ __align__(16) uint16_t smA[3][128*32];  // 3 x 8 KB
    __shared__ __align__(16) uint16_t smB[3][128*32];  // 3 x 8 KB

    const int tid  = threadIdx.x;
    const int lane = tid & 31;
    const int warp = tid >> 5;
    const int g    = lane >> 2;
    const int tig  = lane & 3;
    const int wm   = warp & 1;
    const int wn   = warp >> 1;
    const int m0   = blockIdx.y * 128;
    const int n0   = blockIdx.x * 128;

    float acc[4][8][4];
    #pragma unroll
    for (int mf=0;mf<4;mf++)
        #pragma unroll
        for (int nf=0;nf<8;nf++)
            #pragma unroll
            for (int q=0;q<4;q++) acc[mf][nf][q]=0.f;

    const uint32_t sA0 = smem_u32(&smA[0][0]);
    const uint32_t sB0 = smem_u32(&smB[0][0]);

    const uint32_t lr  = lane & 7;
    const uint32_t lg1 = (lane >> 3) & 1;
    const uint32_t lg2 = lane >> 4;
    uint32_t aAdr[4];
    #pragma unroll
    for (int mf=0; mf<4; mf++){
        uint32_t row = wm*64 + mf*16 + lr + lg1*8;
        uint32_t rsw = (row >> 1) & 3;
        aAdr[mf] = sA0 + (row<<6) + ((lg2 ^ rsw) << 4);
    }
    uint32_t bAdr[4];
    #pragma unroll
    for (int nfp=0; nfp<4; nfp++){
        uint32_t row = wn*64 + nfp*16 + lg2*8 + lr;
        uint32_t rsw = (row >> 1) & 3;
        bAdr[nfp] = sB0 + (row<<6) + ((lg1 ^ rsw) << 4);
    }

    auto fill = [&](int stage, int chunk){
        const int k0 = chunk * KC;
        const uint32_t so = stage * STGB;
        #pragma unroll
        for (int i=0;i<4;i++){
            int q  = i*128 + tid;
            int r  = q >> 2, ch = q & 3;
            uint32_t phys = (uint32_t)(r<<6) + (uint32_t)((ch ^ ((r>>1)&3)) << 4) + so;
            const uint16_t* ga = A + (size_t)(m0+r)*K + k0 + ch*8;
            const uint16_t* gb = B + (size_t)(n0+r)*K + k0 + ch*8;
            uint32_t da = sA0 + phys, db = sB0 + phys;
            asm volatile("cp.async.cg.shared.global [%0], [%1], 16;" :: "r"(da), "l"(ga));
            asm volatile("cp.async.cg.shared.global [%0], [%1], 16;" :: "r"(db), "l"(gb));
        }
        asm volatile("cp.async.commit_group;" ::: "memory");
    };

    fill(0, 0);
    fill(1, 1);
    int stage = 0;
    #pragma unroll 1
    for (int c = 0; c < NC; c++){
        asm volatile("cp.async.wait_group 1;" ::: "memory");
        __syncthreads();
        if (c+2 < NC){
            int ns = stage + 2; if (ns >= 3) ns -= 3;
            fill(ns, c+2);
        }
        const uint32_t so = stage * STGB;
        #pragma unroll
        for (int s=0; s<2; s++){
            const uint32_t sx = (uint32_t)(s << 5);
            uint32_t ar[4][4];
            #pragma unroll
            for (int mf=0; mf<4; mf++) ldsm4(ar[mf], (aAdr[mf] ^ sx) + so);
            #pragma unroll
            for (int nfp=0; nfp<4; nfp++){
                uint32_t br[4];
                ldsm4(br, (bAdr[nfp] ^ sx) + so);
                #pragma unroll
                for (int mf=0; mf<4; mf++){
                    mma_f16(acc[mf][2*nfp  ], ar[mf], br    );
                    mma_f16(acc[mf][2*nfp+1], ar[mf], br + 2);
                }
            }
        }
        stage++; if (stage >= 3) stage = 0;
    }

    // ---------------- epilogue ----------------
    #pragma unroll
    for (int mf=0; mf<4; mf++){
        const int r0 = m0 + wm*64 + mf*16 + g;
        #pragma unroll
        for (int nf=0; nf<8; nf++){
            const int col = n0 + wn*64 + nf*8 + 2*tig;
            const float* cc = acc[mf][nf];
            if (MODE == 0){
                int bin = col >> 1;
                g_big[(size_t)r0*384 + bin]     = sqrtf(cc[0]*cc[0] + cc[1]*cc[1]);
                g_big[(size_t)(r0+8)*384 + bin] = sqrtf(cc[2]*cc[2] + cc[3]*cc[3]);
            } else if (MODE == 2){
                float b0 = __ldg(&bias[col]), b1 = __ldg(&bias[col+1]);
                *(float2*)(g_xn + (size_t)r0*N + col)     = make_float2(cc[0]+b0, cc[1]+b1);
                *(float2*)(g_xn + (size_t)(r0+8)*N + col) = make_float2(cc[2]+b0, cc[3]+b1);
            } else {
                float b0 = __ldg(&bias[col]), b1 = __ldg(&bias[col+1]);
                #pragma unroll
                for (int hrow=0; hrow<2; hrow++){
                    float v0 = gelu_f(cc[hrow*2+0] + b0);
                    float v1 = gelu_f(cc[hrow*2+1] + b1);
                    __half h0 = __float2half(v0), h1 = __float2half(v1);
                    uint32_t hw = ((uint32_t)*(unsigned short*)&h1 << 16) | *(unsigned short*)&h0;
                    size_t o = (size_t)(r0 + hrow*8)*N + col;
                    *(uint32_t*)(g_g1h + o) = hw;
                }
            }
        }
    }
}

// ---------------- BatchNorm over batch dim ----------------------------------
template<int MODE>
__global__ void bn_stats_kernel(const float* __restrict__ srcArg){
    const float* src = (MODE==0) ? srcArg : g_fused;
    int c = blockIdx.x*256 + threadIdx.x;
    float s=0.f, sq=0.f;
    for (int b=0;b<Bsz;b++){
        float v = src[(size_t)b*CC + c];
        s += v; sq += v*v;
    }
    float m = s*(1.0f/Bsz);
    float var = sq*(1.0f/Bsz) - m*m;
    g_mean[c]=m;
    g_rstd[c]=rsqrtf(var+1e-5f);
}

// fused BN1-apply + fp16 cast + transpose
__global__ void bn_trans_kernel(const float* __restrict__ x, const float* __restrict__ gg,
                                const float* __restrict__ bb){
    __shared__ float tile[32][33];
    int b  = blockIdx.z;
    int l0 = blockIdx.x*32, f0 = blockIdx.y*32;
    int tx = threadIdx.x, ty = threadIdx.y;
    const float* ib = x + (size_t)b*CC;
    #pragma unroll
    for (int i=0;i<4;i++){
        int c = (f0 + ty + i*8)*LLEN + l0 + tx;
        float v = (ib[c]-g_mean[c])*g_rstd[c]*gg[c]+bb[c];
        tile[ty+i*8][tx] = v;
        g_xnh[(size_t)b*CC + c] = __float2half(v);
    }
    __syncthreads();
    #pragma unroll
    for (int i=0;i<4;i++){
        int l = l0 + ty + i*8, fn = f0 + tx;
        g_xt[((size_t)(b*LLEN + l))*FND + fn] = tile[tx][ty+i*8];
    }
}

// final BN2 apply
__global__ void bn_apply_kernel(float* __restrict__ dst, const float* __restrict__ gg,
                                const float* __restrict__ bb){
    int idx = blockIdx.x*256 + threadIdx.x;
    int c = idx % CC;
    dst[idx] = (g_fused[idx]-g_mean[c])*g_rstd[c]*gg[c]+bb[c];
}

// ---------------- DFT trig table: interleaved (cos,sin) per bin, fp16 -------
__global__ void trig_kernel(){
    int idx = blockIdx.x*256 + threadIdx.x;
    if (idx >= DFT_N*LLEN) return;
    int n = idx / LLEN, t = idx % LLEN;
    int bin = (n >> 1) + 1;
    int m = (bin*t) % LLEN;                 // exact arg reduction
    float xang = (float)m * (1.0f/384.0f);  // cos(pi*x), x in [0,2)
    float v = ((n & 1) == 0) ? cospif(xang) : sinpif(xang);
    g_trigh[idx] = __float2half(v);
}

// ---------------- weight transpose (fp16) -----------------------------------
__global__ void wt1_kernel(const float* __restrict__ W){   // Wp1 (512x1024) -> [1024][512]
    int idx = blockIdx.x*256 + threadIdx.x;
    int n = idx >> 9, k = idx & 511;
    g_wp1h[idx] = __float2half(W[k*1024 + n]);
}
__global__ void wt2_kernel(const float* __restrict__ W){   // Wp2 (1024x512) -> [512][1024]
    int idx = blockIdx.x*256 + threadIdx.x;
    int n = idx >> 10, k = idx & 1023;
    g_wp2h[idx] = __float2half(W[k*512 + n]);
}

// ---------------- frequency magnitude reduction (deterministic) -------------
__global__ void freq_part_kernel(){
    int k = threadIdx.x;
    if (k >= 384) return;
    int r0 = blockIdx.x * 256;
    float s = 0.f;
    for (int r = r0; r < r0+256; r++)
        s += g_big[(size_t)r*384 + k];
    g_part[blockIdx.x*384 + k] = s;
}
__global__ void freq_final_kernel(){
    int k = threadIdx.x;
    if (k == 384) g_freq[0] = 0.0f;
    if (k >= 384) return;
    float s = 0.f;
    for (int i=0;i<128;i++) s += g_part[i*384 + k];
    g_freq[k+1] = s * (1.0f/32768.0f);
}

// ---------------- top-k + period setup + used-row masks (parallel) ----------
__global__ void __launch_bounds__(768)
setup_kernel(const float* __restrict__ fw){
    __shared__ uint32_t sm[3][96];
    __shared__ int sT2[3];
    int t = threadIdx.x;
    if (t == 0){
        int idx[3];
        for (int s=0;s<3;s++){
            float best = -1.0e30f; int bi = 0;
            for (int i=0;i<NBINS;i++){
                bool skip=false;
                for (int q=0;q<s;q++) if (idx[q]==i) skip=true;
                if (skip) continue;
                float v = g_freq[i];
                if (v > best){ best=v; bi=i; }
            }
            idx[s]=bi;
        }
        int periods[3]; int np_=0;
        for (int s=0;s<3;s++){
            if (idx[s] > 0){
                int raw = LLEN / idx[s];
                if (raw > 0){
                    int p = raw;
                    if (p > LLEN/2) p = LLEN/2;
                    if (p < 4) p = 4;
                    periods[np_++] = p;
                }
            }
        }
        if (np_ == 0){ periods[0]=LLEN/4; periods[1]=LLEN/8; periods[2]=LLEN/16; np_=3; }
        else if (np_ < 3){
            int defs[3]={LLEN/4, LLEN/8, LLEN/16};
            for (int d=0; d<3 && np_<3; d++){
                bool in=false;
                for (int q=0;q<np_;q++) if (periods[q]==defs[d]) in=true;
                if (!in) periods[np_++]=defs[d];
            }
        }
        for (int s=0;s<3;s++){
            int p = periods[s];
            int n = (LLEN-p)/p + 1;
            g_pp[s]=p; g_pn[s]=n; g_poff[s]=LLEN - p*n;
            sT2[s] = n*16;
        }
        float m = fmaxf(fw[0], fmaxf(fw[1], fw[2]));
        float e0=expf(fw[0]-m), e1=expf(fw[1]-m), e2=expf(fw[2]-m);
        float inv = 1.0f/(e0+e1+e2);
        g_pw[0]=e0*inv; g_pw[1]=e1*inv; g_pw[2]=e2*inv;
    }
    if (t < 288) sm[t/96][t%96] = 0u;
    __syncthreads();
    #pragma unroll
    for (int s=0;s<3;s++){
        int T2 = sT2[s];
        float pos = pos_of(t, T2);
        int lo = (int)floorf(pos);
        int hi = min(lo+1, T2-1);
        atomicOr(&sm[s][lo>>5], 1u << (lo & 31));
        atomicOr(&sm[s][hi>>5], 1u << (hi & 31));
    }
    __syncthreads();
    if (t < 288) g_mask[t/96][t%96] = sm[t/96][t%96];
}

// ---------------- fold input-resize into W1:  M1 = R(p->16) @ W1  -----------
__global__ void fold_kernel(const float* __restrict__ W1){
    int k = blockIdx.x;
    int p = g_pp[k];
    float scale = (float)p / 16.0f;
    for (int idx = threadIdx.x; idx < p*32; idx += blockDim.x){
        int t = idx >> 5, c = idx & 31;
        float s = 0.f;
        for (int j=0;j<16;j++){
            float pos = (j + 0.5f)*scale - 0.5f;
            pos = fminf(fmaxf(pos, 0.f), (float)(p-1));
            int lo = (int)floorf(pos);
            int hi = min(lo+1, p-1);
            float w = pos - (float)lo;
            float coef = (lo==t ? (1.0f-w) : 0.0f) + (hi==t ? w : 0.0f);
            s += coef * W1[j*32 + c];
        }
        g_M1[k][idx] = s;
    }
}

// ---------------- patch mixer (all 3 branches; z = branch) ------------------
// Stage-2 compute AND store gated by the exact used-row bitmask.
// Sparse path uses a transposed W2 copy in smem so per-column dot products
// are vectorized (8x LDS.128), fixing R15's scalar-LDS regression.
__global__ void __launch_bounds__(512)
mixer_kernel(const float* __restrict__ b1, const float* __restrict__ W2,
             const float* __restrict__ b2)
{
    int patch = blockIdx.x, b = blockIdx.y, kper = blockIdx.z;
    int n = g_pn[kper];
    if (patch >= n) return;
    int p = g_pp[kper], off = g_poff[kper];
    int tid = threadIdx.x;

    __shared__ float sW2[512];    // [c][o] original layout (full path)
    __shared__ float sW2T[512];   // [o][c] transposed (sparse path, vector over c)
    __shared__ float sb1[32], sb2[16];
    sW2[tid] = W2[tid];
    {
        int o = tid >> 5, c = tid & 31;
        sW2T[tid] = W2[c*16 + o];
    }
    if (tid < 32) sb1[tid] = b1[tid];
    if (tid < 16) sb2[tid] = b2[tid];
    __syncthreads();

    uint32_t mask16 = (g_mask[kper][patch>>1] >> ((patch&1)*16)) & 0xFFFFu;
    if (mask16 == 0u) return;

    int fn = tid;
    const float* xp = g_xt + ((size_t)(b*LLEN + off + patch*p))*FND + fn;
    const float4* M1p = reinterpret_cast<const float4*>(&g_M1[kper][0]);
    float acc[32];
    #pragma unroll
    for (int c=0;c<32;c++) acc[c]=0.f;
    for (int t = 0; t < p; t++){
        float x = xp[(size_t)t*FND];
        #pragma unroll
        for (int c4 = 0; c4 < 8; c4++){
            float4 mm = __ldg(&M1p[t*8 + c4]);
            acc[c4*4+0] = fmaf(x, mm.x, acc[c4*4+0]);
            acc[c4*4+1] = fmaf(x, mm.y, acc[c4*4+1]);
            acc[c4*4+2] = fmaf(x, mm.z, acc[c4*4+2]);
            acc[c4*4+3] = fmaf(x, mm.w, acc[c4*4+3]);
        }
    }
    float h[32];
    #pragma unroll
    for (int c=0;c<32;c++) h[c] = gelu_f(acc[c] + sb1[c]);

    __half* h2 = (kper==0) ? g_h2a : (kper==1) ? g_h2b : g_h2c;
    __half* hp = h2 + ((size_t)(b*(NMAX*16) + patch*16))*FND + fn;

    if (mask16 == 0xFFFFu){
        // full tile: vectorized stage-2 over all 16 columns
        float acc2[16];
        #pragma unroll
        for (int o=0;o<16;o++) acc2[o]=0.f;
        #pragma unroll
        for (int c=0;c<32;c++){
            const float4* w = reinterpret_cast<const float4*>(&sW2[c*16]);
            float hc = h[c];
            #pragma unroll
            for (int o4=0;o4<4;o4++){
                float4 ww = w[o4];
                acc2[o4*4+0] = fmaf(hc, ww.x, acc2[o4*4+0]);
                acc2[o4*4+1] = fmaf(hc, ww.y, acc2[o4*4+1]);
                acc2[o4*4+2] = fmaf(hc, ww.z, acc2[o4*4+2]);
                acc2[o4*4+3] = fmaf(hc, ww.w, acc2[o4*4+3]);
            }
        }
        #pragma unroll
        for (int o=0;o<16;o++)
            hp[(size_t)o*FND] = __float2half(gelu_f(acc2[o] + sb2[o]));
    } else {
        // sparse tile: only used columns; vectorized dot via transposed W2.
        // Same ascending-c accumulation order as full path -> bitwise identical.
        #pragma unroll 1
        for (int o=0;o<16;o++){
            if (!((mask16 >> o) & 1u)) continue;
            const float4* wt = reinterpret_cast<const float4*>(&sW2T[o*32]);
            float s = sb2[o];
            #pragma unroll
            for (int c4=0;c4<8;c4++){
                float4 ww = wt[c4];
                s = fmaf(h[c4*4+0], ww.x, s);
                s = fmaf(h[c4*4+1], ww.y, s);
                s = fmaf(h[c4*4+2], ww.z, s);
                s = fmaf(h[c4*4+3], ww.w, s);
            }
            hp[(size_t)o*FND] = __float2half(gelu_f(s));
        }
    }
}

// ---------------- single-pass 3-branch resize + fusion -> fp16 --------------
__global__ void fuse3_kernel(){
    int l = blockIdx.x, b = blockIdx.y, fn = threadIdx.x;
    float tot = 0.f;
    #pragma unroll
    for (int k=0;k<3;k++){
        const __half* h2 = (k==0) ? g_h2a : (k==1) ? g_h2b : g_h2c;
        int n = g_pn[k];
        int T2 = n*16;
        float wk = g_pw[k];
        float pos = pos_of(l, T2);
        int lo = (int)floorf(pos);
        int hi = min(lo+1, T2-1);
        float w = pos - (float)lo;
        const __half* base = h2 + (size_t)b*(NMAX*16)*FND;
        float v = __half2float(base[(size_t)lo*FND + fn])*(1.0f-w)
                + __half2float(base[(size_t)hi*FND + fn])*w;
        tot = fmaf(wk, v, tot);
    }
    size_t oidx = ((size_t)(b*LLEN + l))*FND + fn;
    g_fh[oidx] = __float2half(tot);
}

// ---------------- residual transpose: g_fused(B,FN,L) = x + g_xn(B,L,FN)^T --
__global__ void transpose_res_kernel(const float* __restrict__ add)
{
    __shared__ float tile[32][33];
    int b = blockIdx.z;
    int r0 = blockIdx.y*32, c0 = blockIdx.x*32;
    int tx = threadIdx.x, ty = threadIdx.y;
    const float* ib = g_xn + (size_t)b*CC;
    #pragma unroll
    for (int i=0;i<4;i++)
        tile[ty + i*8][tx] = ib[(size_t)(r0 + ty + i*8)*FND + c0 + tx];
    __syncthreads();
    #pragma unroll
    for (int i=0;i<4;i++){
        size_t o = (size_t)b*CC + (size_t)(c0 + ty + i*8)*LLEN + r0 + tx;
        g_fused[o] = tile[tx][ty + i*8] + add[o];
    }
}

// ---------------- host launcher (ONLY kernel launches) ----------------------
extern "C" void kernel_launch(void* const* d_in, const int* in_sizes, int n_in,
                              void* d_out, int out_size)
{
    const float* x    = (const float*)d_in[0];
    const float* gin  = (const float*)d_in[1];
    const float* bin  = (const float*)d_in[2];
    const float* W1   = (const float*)d_in[3];
    const float* b1   = (const float*)d_in[4];
    const float* W2   = (const float*)d_in[5];
    const float* b2   = (const float*)d_in[6];
    const float* fw   = (const float*)d_in[7];
    const float* Wp1  = (const float*)d_in[8];
    const float* bp1  = (const float*)d_in[9];
    const float* Wp2  = (const float*)d_in[10];
    const float* bp2  = (const float*)d_in[11];
    const float* gout = (const float*)d_in[12];
    const float* bout = (const float*)d_in[13];
    float* out = (float*)d_out;

    // launch order keeps gemm_wm<0> at capture index 3 for ncu visibility
    bn_stats_kernel<0><<<CC/256, 256>>>(x);                                    // 0
    trig_kernel<<<(DFT_N*LLEN + 255)/256, 256>>>();                            // 1
    bn_trans_kernel<<<dim3(LLEN/32, FND/32, Bsz), dim3(32,8)>>>(x, gin, bin);  // 2
    gemm_wm<0><<<dim3(DFT_N/128, DFT_M/128), 128>>>(nullptr);                  // 3 <- profiled
    freq_part_kernel<<<128, 512>>>();
    freq_final_kernel<<<1, 512>>>();
    setup_kernel<<<1, 768>>>(fw);
    fold_kernel<<<3, 512>>>(W1);
    wt1_kernel<<<524288/256, 256>>>(Wp1);
    wt2_kernel<<<524288/256, 256>>>(Wp2);

    // all 3 period branches in one launch, then one fused resize+sum
    mixer_kernel<<<dim3(NMAX, Bsz, 3), 512>>>(b1, W2, b2);
    fuse3_kernel<<<dim3(LLEN, Bsz), FND>>>();

    // projection MLP (fp16 single-pass warp-MMA)
    gemm_wm<1><<<dim3(1024/128, PRJ_M/128), 128>>>(bp1);
    gemm_wm<2><<<dim3(512/128,  PRJ_M/128), 128>>>(bp2);

    // residual: g_fused(B,FN,L) = x + g_xn(B,L,FN)^T
    transpose_res_kernel<<<dim3(FND/32, LLEN/32, Bsz), dim3(32,8)>>>(x);

    // BN2 -> d_out
    bn_stats_kernel<1><<<CC/256, 256>>>(nullptr);
    bn_apply_kernel<<<BCN/256, 256>>>(out, gout, bout);
}

// round 17
// speedup vs baseline: 1.0989x; 1.0989x over previous
#include <cuda_runtime.h>
#include <cuda_bf16.h>
#include <cuda_fp16.h>
#include <math.h>
#include <stdint.h>

#define Bsz   64
#define FND   512
#define LLEN  768
#define CC    (FND*LLEN)        /* 393216 */
#define BCN   (Bsz*CC)          /* 25165824 */
#define DFT_N 768               /* 384 bins x (cos,sin) interleaved */
#define NBINS 385
#define NMAX  192               /* max patches (p>=4) */
#define DFT_M 32768             /* B*FN rows */
#define PRJ_M 49152             /* B*L rows */

// ---------------- static device scratch ------------------------------------
__device__ float g_big[DFT_M*384];        // DFT |F| (32768x384) fp32
__device__ float g_xt[BCN];               // xt (B,L,FN)
__device__ float g_fused[BCN];            // out_pre (B,FN,L) for BN2
__device__ __half g_h2a[Bsz*NMAX*16*FND]; // patch-MLP out, branch 0 (fp16)
__device__ __half g_h2b[Bsz*NMAX*16*FND]; // branch 1
__device__ __half g_h2c[Bsz*NMAX*16*FND]; // branch 2
__device__ float g_mean[CC];
__device__ float g_rstd[CC];
__device__ float g_part[128*384];
__device__ float g_freq[NBINS];
__device__ float g_M1[3][384*32];
__device__ int   g_pp[3], g_pn[3], g_poff[3];
__device__ float g_pw[3];
__device__ uint32_t g_mask[3][96];        // used-row bitmask per branch

// fp16 GEMM operands (single pass everywhere)
__device__ __half g_xnh[BCN];             // DFT A (32768x768)
__device__ __half g_trigh[DFT_N*LLEN];    // DFT B [768][768]
__device__ __half g_fh[BCN];              // proj1 A (49152x512)
__device__ __half g_g1h[PRJ_M*1024];      // proj1 out / proj2 A
__device__ __half g_wp1h[1024*512];       // Wp1^T
__device__ __half g_wp2h[512*1024];       // Wp2^T

__device__ __forceinline__ float gelu_f(float x){
    return 0.5f*x*(1.0f + erff(x*0.70710678118654752440f));
}
__device__ __forceinline__ uint32_t smem_u32(const void* p){
    uint32_t a;
    asm("{ .reg .u64 t; cvta.to.shared.u64 t, %1; cvt.u32.u64 %0, t; }" : "=r"(a) : "l"(p));
    return a;
}
// shared resize-position helper (mask & fuse3 bit-identical by construction)
__device__ __forceinline__ float pos_of(int l, int T2){
    float s = (float)T2 * (1.0f/768.0f);
    float pos = fmaf((float)l + 0.5f, s, -0.5f);
    return fminf(fmaxf(pos, 0.0f), (float)(T2-1));
}

// ================= warp-MMA GEMM (m16n8k16 fp16 + ldmatrix) ================
// Block 128x128, 4 warps (2x2), warp tile 64x64, 3-stage cp.async pipeline,
// XOR-swizzled 64B smem rows. Single fp16 pass for all modes.
// MODE 0: DFT   A=g_xnh  B=g_trigh K=768  N=768   out |F| fp32 g_big
// MODE 1: proj1 A=g_fh   B=g_wp1h  K=512  N=1024  out fp16 g_g1h (bias+gelu)
// MODE 2: proj2 A=g_g1h  B=g_wp2h  K=1024 N=512   out g_fused transposed + residual
#define KC     32
#define STGB   8192

__device__ __forceinline__ void mma_f16(float* c, const uint32_t* a, const uint32_t* b){
    asm volatile(
        "mma.sync.aligned.m16n8k16.row.col.f32.f16.f16.f32 "
        "{%0,%1,%2,%3}, {%4,%5,%6,%7}, {%8,%9}, {%0,%1,%2,%3};"
        : "+f"(c[0]), "+f"(c[1]), "+f"(c[2]), "+f"(c[3])
        : "r"(a[0]), "r"(a[1]), "r"(a[2]), "r"(a[3]), "r"(b[0]), "r"(b[1]));
}
__device__ __forceinline__ void ldsm4(uint32_t* r, uint32_t addr){
    asm volatile("ldmatrix.sync.aligned.m8n8.x4.shared.b16 {%0,%1,%2,%3}, [%4];"
        : "=r"(r[0]), "=r"(r[1]), "=r"(r[2]), "=r"(r[3]) : "r"(addr));
}

template<int MODE>
__global__ void __launch_bounds__(128, 3)
gemm_wm(const float* __restrict__ bias, const float* __restrict__ xres)
{
    constexpr int K  = (MODE==0) ? 768 : (MODE==1) ? 512 : 1024;
    constexpr int N  = (MODE==0) ? 768 : (MODE==1) ? 1024 : 512;
    constexpr int NC = K / KC;

    const uint16_t* A = (MODE==0) ? (const uint16_t*)g_xnh :
                        (MODE==1) ? (const uint16_t*)g_fh  : (const uint16_t*)g_g1h;
    const uint16_t* B = (MODE==0) ? (const uint16_t*)g_trigh :
                        (MODE==1) ? (const uint16_t*)g_wp1h : (const uint16_t*)g_wp2h;

    __shared__ __align__(16) uint16_t smA[3][128*32];  // 3 x 8 KB
    __shared__ __align__(16) uint16_t smB[3][128*32];  // 3 x 8 KB

    const int tid  = threadIdx.x;
    const int lane = tid & 31;
    const int warp = tid >> 5;
    const int g    = lane >> 2;
    const int tig  = lane & 3;
    const int wm   = warp & 1;
    const int wn   = warp >> 1;
    const int m0   = blockIdx.y * 128;
    const int n0   = blockIdx.x * 128;

    float acc[4][8][4];
    #pragma unroll
    for (int mf=0;mf<4;mf++)
        #pragma unroll
        for (int nf=0;nf<8;nf++)
            #pragma unroll
            for (int q=0;q<4;q++) acc[mf][nf][q]=0.f;

    const uint32_t sA0 = smem_u32(&smA[0][0]);
    const uint32_t sB0 = smem_u32(&smB[0][0]);

    const uint32_t lr  = lane & 7;
    const uint32_t lg1 = (lane >> 3) & 1;
    const uint32_t lg2 = lane >> 4;
    uint32_t aAdr[4];
    #pragma unroll
    for (int mf=0; mf<4; mf++){
        uint32_t row = wm*64 + mf*16 + lr + lg1*8;
        uint32_t rsw = (row >> 1) & 3;
        aAdr[mf] = sA0 + (row<<6) + ((lg2 ^ rsw) << 4);
    }
    uint32_t bAdr[4];
    #pragma unroll
    for (int nfp=0; nfp<4; nfp++){
        uint32_t row = wn*64 + nfp*16 + lg2*8 + lr;
        uint32_t rsw = (row >> 1) & 3;
        bAdr[nfp] = sB0 + (row<<6) + ((lg1 ^ rsw) << 4);
    }

    auto fill = [&](int stage, int chunk){
        const int k0 = chunk * KC;
        const uint32_t so = stage * STGB;
        #pragma unroll
        for (int i=0;i<4;i++){
            int q  = i*128 + tid;
            int r  = q >> 2, ch = q & 3;
            uint32_t phys = (uint32_t)(r<<6) + (uint32_t)((ch ^ ((r>>1)&3)) << 4) + so;
            const uint16_t* ga = A + (size_t)(m0+r)*K + k0 + ch*8;
            const uint16_t* gb = B + (size_t)(n0+r)*K + k0 + ch*8;
            uint32_t da = sA0 + phys, db = sB0 + phys;
            asm volatile("cp.async.cg.shared.global [%0], [%1], 16;" :: "r"(da), "l"(ga));
            asm volatile("cp.async.cg.shared.global [%0], [%1], 16;" :: "r"(db), "l"(gb));
        }
        asm volatile("cp.async.commit_group;" ::: "memory");
    };

    fill(0, 0);
    fill(1, 1);
    int stage = 0;
    #pragma unroll 1
    for (int c = 0; c < NC; c++){
        asm volatile("cp.async.wait_group 1;" ::: "memory");
        __syncthreads();
        if (c+2 < NC){
            int ns = stage + 2; if (ns >= 3) ns -= 3;
            fill(ns, c+2);
        }
        const uint32_t so = stage * STGB;
        #pragma unroll
        for (int s=0; s<2; s++){
            const uint32_t sx = (uint32_t)(s << 5);
            uint32_t ar[4][4];
            #pragma unroll
            for (int mf=0; mf<4; mf++) ldsm4(ar[mf], (aAdr[mf] ^ sx) + so);
            #pragma unroll
            for (int nfp=0; nfp<4; nfp++){
                uint32_t br[4];
                ldsm4(br, (bAdr[nfp] ^ sx) + so);
                #pragma unroll
                for (int mf=0; mf<4; mf++){
                    mma_f16(acc[mf][2*nfp  ], ar[mf], br    );
                    mma_f16(acc[mf][2*nfp+1], ar[mf], br + 2);
                }
            }
        }
        stage++; if (stage >= 3) stage = 0;
    }

    // ---------------- epilogue ----------------
    #pragma unroll
    for (int mf=0; mf<4; mf++){
        const int r0 = m0 + wm*64 + mf*16 + g;
        #pragma unroll
        for (int nf=0; nf<8; nf++){
            const int col = n0 + wn*64 + nf*8 + 2*tig;
            const float* cc = acc[mf][nf];
            if (MODE == 0){
                int bin = col >> 1;
                g_big[(size_t)r0*384 + bin]     = sqrtf(cc[0]*cc[0] + cc[1]*cc[1]);
                g_big[(size_t)(r0+8)*384 + bin] = sqrtf(cc[2]*cc[2] + cc[3]*cc[3]);
            } else if (MODE == 2){
                // fused transpose + residual: row r = b*768+l, write (b, col, l)
                float b0 = __ldg(&bias[col]), b1 = __ldg(&bias[col+1]);
                int b  = r0 / LLEN, l = r0 - b*LLEN;   // tile never straddles b (768%128==0)
                size_t o0 = (size_t)b*CC + (size_t)col*LLEN + l;
                g_fused[o0]          = (cc[0]+b0) + __ldg(&xres[o0]);
                g_fused[o0+LLEN]     = (cc[1]+b1) + __ldg(&xres[o0+LLEN]);
                g_fused[o0+8]        = (cc[2]+b0) + __ldg(&xres[o0+8]);
                g_fused[o0+LLEN+8]   = (cc[3]+b1) + __ldg(&xres[o0+LLEN+8]);
            } else {
                float b0 = __ldg(&bias[col]), b1 = __ldg(&bias[col+1]);
                #pragma unroll
                for (int hrow=0; hrow<2; hrow++){
                    float v0 = gelu_f(cc[hrow*2+0] + b0);
                    float v1 = gelu_f(cc[hrow*2+1] + b1);
                    __half h0 = __float2half(v0), h1 = __float2half(v1);
                    uint32_t hw = ((uint32_t)*(unsigned short*)&h1 << 16) | *(unsigned short*)&h0;
                    size_t o = (size_t)(r0 + hrow*8)*N + col;
                    *(uint32_t*)(g_g1h + o) = hw;
                }
            }
        }
    }
}

// ---------------- BatchNorm over batch dim ----------------------------------
template<int MODE>
__global__ void bn_stats_kernel(const float* __restrict__ srcArg){
    const float* src = (MODE==0) ? srcArg : g_fused;
    int c = blockIdx.x*256 + threadIdx.x;
    float s=0.f, sq=0.f;
    for (int b=0;b<Bsz;b++){
        float v = src[(size_t)b*CC + c];
        s += v; sq += v*v;
    }
    float m = s*(1.0f/Bsz);
    float var = sq*(1.0f/Bsz) - m*m;
    g_mean[c]=m;
    g_rstd[c]=rsqrtf(var+1e-5f);
}

// fused BN1-apply + fp16 cast + transpose
__global__ void bn_trans_kernel(const float* __restrict__ x, const float* __restrict__ gg,
                                const float* __restrict__ bb){
    __shared__ float tile[32][33];
    int b  = blockIdx.z;
    int l0 = blockIdx.x*32, f0 = blockIdx.y*32;
    int tx = threadIdx.x, ty = threadIdx.y;
    const float* ib = x + (size_t)b*CC;
    #pragma unroll
    for (int i=0;i<4;i++){
        int c = (f0 + ty + i*8)*LLEN + l0 + tx;
        float v = (ib[c]-g_mean[c])*g_rstd[c]*gg[c]+bb[c];
        tile[ty+i*8][tx] = v;
        g_xnh[(size_t)b*CC + c] = __float2half(v);
    }
    __syncthreads();
    #pragma unroll
    for (int i=0;i<4;i++){
        int l = l0 + ty + i*8, fn = f0 + tx;
        g_xt[((size_t)(b*LLEN + l))*FND + fn] = tile[tx][ty+i*8];
    }
}

// final BN2 apply
__global__ void bn_apply_kernel(float* __restrict__ dst, const float* __restrict__ gg,
                                const float* __restrict__ bb){
    int idx = blockIdx.x*256 + threadIdx.x;
    int c = idx % CC;
    dst[idx] = (g_fused[idx]-g_mean[c])*g_rstd[c]*gg[c]+bb[c];
}

// ---------------- DFT trig table: interleaved (cos,sin) per bin, fp16 -------
__global__ void trig_kernel(){
    int idx = blockIdx.x*256 + threadIdx.x;
    if (idx >= DFT_N*LLEN) return;
    int n = idx / LLEN, t = idx % LLEN;
    int bin = (n >> 1) + 1;
    int m = (bin*t) % LLEN;                 // exact arg reduction
    float xang = (float)m * (1.0f/384.0f);  // cos(pi*x), x in [0,2)
    float v = ((n & 1) == 0) ? cospif(xang) : sinpif(xang);
    g_trigh[idx] = __float2half(v);
}

// ---------------- weight transpose (fp16) -----------------------------------
__global__ void wt1_kernel(const float* __restrict__ W){   // Wp1 (512x1024) -> [1024][512]
    int idx = blockIdx.x*256 + threadIdx.x;
    int n = idx >> 9, k = idx & 511;
    g_wp1h[idx] = __float2half(W[k*1024 + n]);
}
__global__ void wt2_kernel(const float* __restrict__ W){   // Wp2 (1024x512) -> [512][1024]
    int idx = blockIdx.x*256 + threadIdx.x;
    int n = idx >> 10, k = idx & 1023;
    g_wp2h[idx] = __float2half(W[k*512 + n]);
}

// ---------------- frequency magnitude reduction (deterministic) -------------
__global__ void freq_part_kernel(){
    int k = threadIdx.x;
    if (k >= 384) return;
    int r0 = blockIdx.x * 256;
    float s = 0.f;
    for (int r = r0; r < r0+256; r++)
        s += g_big[(size_t)r*384 + k];
    g_part[blockIdx.x*384 + k] = s;
}
__global__ void freq_final_kernel(){
    int k = threadIdx.x;
    if (k == 384) g_freq[0] = 0.0f;
    if (k >= 384) return;
    float s = 0.f;
    for (int i=0;i<128;i++) s += g_part[i*384 + k];
    g_freq[k+1] = s * (1.0f/32768.0f);
}

// ---------------- top-k + period setup + used-row masks (parallel) ----------
__global__ void __launch_bounds__(768)
setup_kernel(const float* __restrict__ fw){
    __shared__ uint32_t sm[3][96];
    __shared__ int sT2[3];
    int t = threadIdx.x;
    if (t == 0){
        int idx[3];
        for (int s=0;s<3;s++){
            float best = -1.0e30f; int bi = 0;
            for (int i=0;i<NBINS;i++){
                bool skip=false;
                for (int q=0;q<s;q++) if (idx[q]==i) skip=true;
                if (skip) continue;
                float v = g_freq[i];
                if (v > best){ best=v; bi=i; }
            }
            idx[s]=bi;
        }
        int periods[3]; int np_=0;
        for (int s=0;s<3;s++){
            if (idx[s] > 0){
                int raw = LLEN / idx[s];
                if (raw > 0){
                    int p = raw;
                    if (p > LLEN/2) p = LLEN/2;
                    if (p < 4) p = 4;
                    periods[np_++] = p;
                }
            }
        }
        if (np_ == 0){ periods[0]=LLEN/4; periods[1]=LLEN/8; periods[2]=LLEN/16; np_=3; }
        else if (np_ < 3){
            int defs[3]={LLEN/4, LLEN/8, LLEN/16};
            for (int d=0; d<3 && np_<3; d++){
                bool in=false;
                for (int q=0;q<np_;q++) if (periods[q]==defs[d]) in=true;
                if (!in) periods[np_++]=defs[d];
            }
        }
        for (int s=0;s<3;s++){
            int p = periods[s];
            int n = (LLEN-p)/p + 1;
            g_pp[s]=p; g_pn[s]=n; g_poff[s]=LLEN - p*n;
            sT2[s] = n*16;
        }
        float m = fmaxf(fw[0], fmaxf(fw[1], fw[2]));
        float e0=expf(fw[0]-m), e1=expf(fw[1]-m), e2=expf(fw[2]-m);
        float inv = 1.0f/(e0+e1+e2);
        g_pw[0]=e0*inv; g_pw[1]=e1*inv; g_pw[2]=e2*inv;
    }
    if (t < 288) sm[t/96][t%96] = 0u;
    __syncthreads();
    #pragma unroll
    for (int s=0;s<3;s++){
        int T2 = sT2[s];
        float pos = pos_of(t, T2);
        int lo = (int)floorf(pos);
        int hi = min(lo+1, T2-1);
        atomicOr(&sm[s][lo>>5], 1u << (lo & 31));
        atomicOr(&sm[s][hi>>5], 1u << (hi & 31));
    }
    __syncthreads();
    if (t < 288) g_mask[t/96][t%96] = sm[t/96][t%96];
}

// ---------------- fold input-resize into W1:  M1 = R(p->16) @ W1  -----------
__global__ void fold_kernel(const float* __restrict__ W1){
    int k = blockIdx.x;
    int p = g_pp[k];
    float scale = (float)p / 16.0f;
    for (int idx = threadIdx.x; idx < p*32; idx += blockDim.x){
        int t = idx >> 5, c = idx & 31;
        float s = 0.f;
        for (int j=0;j<16;j++){
            float pos = (j + 0.5f)*scale - 0.5f;
            pos = fminf(fmaxf(pos, 0.f), (float)(p-1));
            int lo = (int)floorf(pos);
            int hi = min(lo+1, p-1);
            float w = pos - (float)lo;
            float coef = (lo==t ? (1.0f-w) : 0.0f) + (hi==t ? w : 0.0f);
            s += coef * W1[j*32 + c];
        }
        g_M1[k][idx] = s;
    }
}

// ---------------- patch mixer (all 3 branches; z = branch) ------------------
// R14 form: full vectorized stage-2; bitmask gates stores only.
__global__ void __launch_bounds__(512)
mixer_kernel(const float* __restrict__ b1, const float* __restrict__ W2,
             const float* __restrict__ b2)
{
    int patch = blockIdx.x, b = blockIdx.y, kper = blockIdx.z;
    int n = g_pn[kper];
    if (patch >= n) return;
    int p = g_pp[kper], off = g_poff[kper];
    int tid = threadIdx.x;

    __shared__ float sW2[512], sb1[32], sb2[16];
    sW2[tid] = W2[tid];
    if (tid < 32) sb1[tid] = b1[tid];
    if (tid < 16) sb2[tid] = b2[tid];
    __syncthreads();

    uint32_t mask16 = (g_mask[kper][patch>>1] >> ((patch&1)*16)) & 0xFFFFu;
    if (mask16 == 0u) return;

    int fn = tid;
    const float* xp = g_xt + ((size_t)(b*LLEN + off + patch*p))*FND + fn;
    const float4* M1p = reinterpret_cast<const float4*>(&g_M1[kper][0]);
    float acc[32];
    #pragma unroll
    for (int c=0;c<32;c++) acc[c]=0.f;
    for (int t = 0; t < p; t++){
        float x = xp[(size_t)t*FND];
        #pragma unroll
        for (int c4 = 0; c4 < 8; c4++){
            float4 mm = __ldg(&M1p[t*8 + c4]);
            acc[c4*4+0] = fmaf(x, mm.x, acc[c4*4+0]);
            acc[c4*4+1] = fmaf(x, mm.y, acc[c4*4+1]);
            acc[c4*4+2] = fmaf(x, mm.z, acc[c4*4+2]);
            acc[c4*4+3] = fmaf(x, mm.w, acc[c4*4+3]);
        }
    }
    float h[32];
    #pragma unroll
    for (int c=0;c<32;c++) h[c] = gelu_f(acc[c] + sb1[c]);

    float acc2[16];
    #pragma unroll
    for (int o=0;o<16;o++) acc2[o]=0.f;
    #pragma unroll
    for (int c=0;c<32;c++){
        const float4* w = reinterpret_cast<const float4*>(&sW2[c*16]);
        float hc = h[c];
        #pragma unroll
        for (int o4=0;o4<4;o4++){
            float4 ww = w[o4];
            acc2[o4*4+0] = fmaf(hc, ww.x, acc2[o4*4+0]);
            acc2[o4*4+1] = fmaf(hc, ww.y, acc2[o4*4+1]);
            acc2[o4*4+2] = fmaf(hc, ww.z, acc2[o4*4+2]);
            acc2[o4*4+3] = fmaf(hc, ww.w, acc2[o4*4+3]);
        }
    }
    __half* h2 = (kper==0) ? g_h2a : (kper==1) ? g_h2b : g_h2c;
    __half* hp = h2 + ((size_t)(b*(NMAX*16) + patch*16))*FND + fn;
    #pragma unroll
    for (int o=0;o<16;o++){
        if ((mask16 >> o) & 1u)
            hp[(size_t)o*FND] = __float2half(gelu_f(acc2[o] + sb2[o]));
    }
}

// ---------------- single-pass 3-branch resize + fusion -> fp16 --------------
__global__ void fuse3_kernel(){
    int l = blockIdx.x, b = blockIdx.y, fn = threadIdx.x;
    float tot = 0.f;
    #pragma unroll
    for (int k=0;k<3;k++){
        const __half* h2 = (k==0) ? g_h2a : (k==1) ? g_h2b : g_h2c;
        int n = g_pn[k];
        int T2 = n*16;
        float wk = g_pw[k];
        float pos = pos_of(l, T2);
        int lo = (int)floorf(pos);
        int hi = min(lo+1, T2-1);
        float w = pos - (float)lo;
        const __half* base = h2 + (size_t)b*(NMAX*16)*FND;
        float v = __half2float(base[(size_t)lo*FND + fn])*(1.0f-w)
                + __half2float(base[(size_t)hi*FND + fn])*w;
        tot = fmaf(wk, v, tot);
    }
    size_t oidx = ((size_t)(b*LLEN + l))*FND + fn;
    g_fh[oidx] = __float2half(tot);
}

// ---------------- host launcher (ONLY kernel launches) ----------------------
extern "C" void kernel_launch(void* const* d_in, const int* in_sizes, int n_in,
                              void* d_out, int out_size)
{
    const float* x    = (const float*)d_in[0];
    const float* gin  = (const float*)d_in[1];
    const float* bin  = (const float*)d_in[2];
    const float* W1   = (const float*)d_in[3];
    const float* b1   = (const float*)d_in[4];
    const float* W2   = (const float*)d_in[5];
    const float* b2   = (const float*)d_in[6];
    const float* fw   = (const float*)d_in[7];
    const float* Wp1  = (const float*)d_in[8];
    const float* bp1  = (const float*)d_in[9];
    const float* Wp2  = (const float*)d_in[10];
    const float* bp2  = (const float*)d_in[11];
    const float* gout = (const float*)d_in[12];
    const float* bout = (const float*)d_in[13];
    float* out = (float*)d_out;

    // launch order keeps gemm_wm<0> at capture index 3 for ncu visibility
    bn_stats_kernel<0><<<CC/256, 256>>>(x);                                    // 0
    trig_kernel<<<(DFT_N*LLEN + 255)/256, 256>>>();                            // 1
    bn_trans_kernel<<<dim3(LLEN/32, FND/32, Bsz), dim3(32,8)>>>(x, gin, bin);  // 2
    gemm_wm<0><<<dim3(DFT_N/128, DFT_M/128), 128>>>(nullptr, nullptr);         // 3 <- profiled
    freq_part_kernel<<<128, 512>>>();
    freq_final_kernel<<<1, 512>>>();
    setup_kernel<<<1, 768>>>(fw);
    fold_kernel<<<3, 512>>>(W1);
    wt1_kernel<<<524288/256, 256>>>(Wp1);
    wt2_kernel<<<524288/256, 256>>>(Wp2);

    // all 3 period branches in one launch, then one fused resize+sum
    mixer_kernel<<<dim3(NMAX, Bsz, 3), 512>>>(b1, W2, b2);
    fuse3_kernel<<<dim3(LLEN, Bsz), FND>>>();

    // projection MLP (fp16 single-pass warp-MMA); proj2 fuses transpose+residual
    gemm_wm<1><<<dim3(1024/128, PRJ_M/128), 128>>>(bp1, nullptr);
    gemm_wm<2><<<dim3(512/128,  PRJ_M/128), 128>>>(bp2, x);

    // BN2 -> d_out
    bn_stats_kernel<1><<<CC/256, 256>>>(nullptr);
    bn_apply_kernel<<<BCN/256, 256>>>(out, gout, bout);
}